// round 2
// baseline (speedup 1.0000x reference)
#include <cuda_runtime.h>
#include <math.h>

#define H      2048
#define NH     32
#define NKV    8
#define HD     64
#define GROUPS 4
#define FF     5632
#define BATCH  2
#define SEQ    2048
#define M_TOK  (BATCH*SEQ)

#define ATTN_SMEM (4*64*68*4)

// ---------------- scratch (device globals: allocation-guard safe) ----------------
__device__ float g_xn[M_TOK*H];        // rmsnorm output (reused for both norms)
__device__ float g_q[M_TOK*H];         // Q after proj/rope; attention writes output in-place here
__device__ float g_k[M_TOK*NKV*HD];
__device__ float g_v[M_TOK*NKV*HD];
__device__ float g_hidden[M_TOK*H];    // residual after o-proj
__device__ float g_gate[M_TOK*FF];     // gate proj, then silu(gate)*up in-place

// ---------------- RMSNorm ----------------
__global__ void rmsnorm_kernel(const float* __restrict__ x, const float* __restrict__ w,
                               float* __restrict__ y) {
    int row = blockIdx.x;
    const float4* xr = (const float4*)(x + (size_t)row * H);
    const float4* wv = (const float4*)w;
    float4* yr = (float4*)(y + (size_t)row * H);
    int tid = threadIdx.x;
    float4 a = xr[tid];
    float4 b = xr[tid + 256];
    float ss = a.x*a.x + a.y*a.y + a.z*a.z + a.w*a.w
             + b.x*b.x + b.y*b.y + b.z*b.z + b.w*b.w;
    #pragma unroll
    for (int o = 16; o; o >>= 1) ss += __shfl_xor_sync(0xffffffffu, ss, o);
    __shared__ float ws[8];
    if ((tid & 31) == 0) ws[tid >> 5] = ss;
    __syncthreads();
    float tot = ws[0]+ws[1]+ws[2]+ws[3]+ws[4]+ws[5]+ws[6]+ws[7];
    float r = rsqrtf(tot * (1.0f / (float)H) + 1e-5f);
    float4 w0 = wv[tid], w1 = wv[tid + 256];
    float4 o0, o1;
    o0.x = a.x*r*w0.x; o0.y = a.y*r*w0.y; o0.z = a.z*r*w0.z; o0.w = a.w*r*w0.w;
    o1.x = b.x*r*w1.x; o1.y = b.y*r*w1.y; o1.z = b.z*r*w1.z; o1.w = b.w*r*w1.w;
    yr[tid] = o0;
    yr[tid + 256] = o1;
}

// ---------------- GEMM with binarized weights (packed f32x2 FMA, double-buffered) ----------------
// C[M,N] = A[M,K] @ (aa*clip(kk*W,-1,1))[N,K]^T   (+ epilogue)
// MODE 0: store. MODE 1: store acc + X. MODE 2: store silu(X)*acc (X may alias C).
template<int MODE>
__global__ void __launch_bounds__(256) gemm_binlin(
    const float* __restrict__ A, const float* __restrict__ W,
    const float* X, float* C,
    int N, int K, const float* __restrict__ kkp, const float* __restrict__ aap)
{
    __shared__ __align__(16) float As[2][16][132];
    __shared__ __align__(16) float Bs[2][16][132];
    const float kk = kkp[0];
    const float aa = aap[0];

    int bm = blockIdx.y << 7;
    int bn = blockIdx.x << 7;
    int tid = threadIdx.x;

    // tile-load mapping: conflict-free transposing STS
    int lm = tid & 127;            // row within tile
    int lk = (tid >> 7) << 3;      // k offset: 0 or 8 (each thread loads 8 consecutive k)
    int tr = (tid >> 4) << 3;      // microtile row base
    int tc = (tid & 15) << 3;      // microtile col base

    const float* Ap = A + (size_t)(bm + lm) * K + lk;
    const float* Wp = W + (size_t)(bn + lm) * K + lk;

    unsigned long long acc[8][4];  // 8 rows x 4 col-pairs (each = 2 packed fp32)
    #pragma unroll
    for (int i = 0; i < 8; i++)
        #pragma unroll
        for (int j = 0; j < 4; j++) acc[i][j] = 0ull;

    int nk = K >> 4;

    // prologue: load tile 0, stage into buffer 0
    float4 ra0 = *(const float4*)(Ap);
    float4 ra1 = *(const float4*)(Ap + 4);
    float4 rw0 = *(const float4*)(Wp);
    float4 rw1 = *(const float4*)(Wp + 4);
    {
        As[0][lk+0][lm] = ra0.x; As[0][lk+1][lm] = ra0.y;
        As[0][lk+2][lm] = ra0.z; As[0][lk+3][lm] = ra0.w;
        As[0][lk+4][lm] = ra1.x; As[0][lk+5][lm] = ra1.y;
        As[0][lk+6][lm] = ra1.z; As[0][lk+7][lm] = ra1.w;
        Bs[0][lk+0][lm] = aa * fminf(fmaxf(kk * rw0.x, -1.0f), 1.0f);
        Bs[0][lk+1][lm] = aa * fminf(fmaxf(kk * rw0.y, -1.0f), 1.0f);
        Bs[0][lk+2][lm] = aa * fminf(fmaxf(kk * rw0.z, -1.0f), 1.0f);
        Bs[0][lk+3][lm] = aa * fminf(fmaxf(kk * rw0.w, -1.0f), 1.0f);
        Bs[0][lk+4][lm] = aa * fminf(fmaxf(kk * rw1.x, -1.0f), 1.0f);
        Bs[0][lk+5][lm] = aa * fminf(fmaxf(kk * rw1.y, -1.0f), 1.0f);
        Bs[0][lk+6][lm] = aa * fminf(fmaxf(kk * rw1.z, -1.0f), 1.0f);
        Bs[0][lk+7][lm] = aa * fminf(fmaxf(kk * rw1.w, -1.0f), 1.0f);
    }
    __syncthreads();

    for (int kb = 0; kb < nk; kb++) {
        int cur = kb & 1;
        int nxt = cur ^ 1;
        if (kb + 1 < nk) {
            int ko = (kb + 1) << 4;
            ra0 = *(const float4*)(Ap + ko);
            ra1 = *(const float4*)(Ap + ko + 4);
            rw0 = *(const float4*)(Wp + ko);
            rw1 = *(const float4*)(Wp + ko + 4);
        }

        #pragma unroll
        for (int k = 0; k < 16; k++) {
            float4 a0 = *(const float4*)&As[cur][k][tr];
            float4 a1 = *(const float4*)&As[cur][k][tr + 4];
            ulonglong2 b0 = *(const ulonglong2*)&Bs[cur][k][tc];
            ulonglong2 b1 = *(const ulonglong2*)&Bs[cur][k][tc + 4];
            float ar[8] = {a0.x, a0.y, a0.z, a0.w, a1.x, a1.y, a1.z, a1.w};
            unsigned long long bb[4] = {b0.x, b0.y, b1.x, b1.y};
            #pragma unroll
            for (int i = 0; i < 8; i++) {
                unsigned long long ad;
                asm("mov.b64 %0, {%1, %1};" : "=l"(ad) : "f"(ar[i]));
                #pragma unroll
                for (int j = 0; j < 4; j++)
                    asm("fma.rn.f32x2 %0, %1, %2, %0;"
                        : "+l"(acc[i][j]) : "l"(ad), "l"(bb[j]));
            }
        }

        if (kb + 1 < nk) {
            As[nxt][lk+0][lm] = ra0.x; As[nxt][lk+1][lm] = ra0.y;
            As[nxt][lk+2][lm] = ra0.z; As[nxt][lk+3][lm] = ra0.w;
            As[nxt][lk+4][lm] = ra1.x; As[nxt][lk+5][lm] = ra1.y;
            As[nxt][lk+6][lm] = ra1.z; As[nxt][lk+7][lm] = ra1.w;
            Bs[nxt][lk+0][lm] = aa * fminf(fmaxf(kk * rw0.x, -1.0f), 1.0f);
            Bs[nxt][lk+1][lm] = aa * fminf(fmaxf(kk * rw0.y, -1.0f), 1.0f);
            Bs[nxt][lk+2][lm] = aa * fminf(fmaxf(kk * rw0.z, -1.0f), 1.0f);
            Bs[nxt][lk+3][lm] = aa * fminf(fmaxf(kk * rw0.w, -1.0f), 1.0f);
            Bs[nxt][lk+4][lm] = aa * fminf(fmaxf(kk * rw1.x, -1.0f), 1.0f);
            Bs[nxt][lk+5][lm] = aa * fminf(fmaxf(kk * rw1.y, -1.0f), 1.0f);
            Bs[nxt][lk+6][lm] = aa * fminf(fmaxf(kk * rw1.z, -1.0f), 1.0f);
            Bs[nxt][lk+7][lm] = aa * fminf(fmaxf(kk * rw1.w, -1.0f), 1.0f);
        }
        __syncthreads();
    }

    // epilogue
    #pragma unroll
    for (int i = 0; i < 8; i++) {
        size_t off = (size_t)(bm + tr + i) * N + bn + tc;
        float2 p0 = *reinterpret_cast<float2*>(&acc[i][0]);
        float2 p1 = *reinterpret_cast<float2*>(&acc[i][1]);
        float2 p2 = *reinterpret_cast<float2*>(&acc[i][2]);
        float2 p3 = *reinterpret_cast<float2*>(&acc[i][3]);
        float v[8] = {p0.x, p0.y, p1.x, p1.y, p2.x, p2.y, p3.x, p3.y};
        #pragma unroll
        for (int j4 = 0; j4 < 8; j4 += 4) {
            float v0 = v[j4+0], v1 = v[j4+1], v2 = v[j4+2], v3 = v[j4+3];
            if (MODE == 1) {
                const float4 xr = *(const float4*)(X + off + j4);
                v0 += xr.x; v1 += xr.y; v2 += xr.z; v3 += xr.w;
            } else if (MODE == 2) {
                const float4 gr = *(const float4*)(X + off + j4);
                v0 *= gr.x / (1.0f + expf(-gr.x));
                v1 *= gr.y / (1.0f + expf(-gr.y));
                v2 *= gr.z / (1.0f + expf(-gr.z));
                v3 *= gr.w / (1.0f + expf(-gr.w));
            }
            float4 r; r.x = v0; r.y = v1; r.z = v2; r.w = v3;
            *(float4*)(C + off + j4) = r;
        }
    }
}

// ---------------- RoPE (in-place on g_q and g_k) ----------------
__global__ void rope_kernel(const int* __restrict__ pos_ids) {
    int gid = blockIdx.x * blockDim.x + threadIdx.x;
    int d = gid & 31;
    int slot = gid >> 5;
    int head = slot % (NH + NKV);
    int tok = slot / (NH + NKV);
    if (tok >= M_TOK) return;
    float p = (float)pos_ids[tok];
    float inv = powf(10000.0f, -(float)d * (1.0f / 32.0f));
    float ang = p * inv;
    float s, c;
    sincosf(ang, &s, &c);
    float* base;
    if (head < NH) base = g_q + (((size_t)tok * NH + head) << 6);
    else           base = g_k + (((size_t)tok * NKV + (head - NH)) << 6);
    float x1 = base[d];
    float x2 = base[d + 32];
    base[d]      = x1 * c - x2 * s;
    base[d + 32] = x2 * c + x1 * s;
}

// ---------------- Flash attention (causal, GQA), output in-place into g_q ----------------
__global__ void __launch_bounds__(256, 1) attn_kernel() {
    extern __shared__ float sm[];
    float* Qt  = sm;                // [64][68] (q,d), pre-scaled by 1/8
    float* KtT = sm + 64 * 68;      // [64][68] (d,kc) transposed
    float* Vt  = sm + 2 * 64 * 68;  // [64][68] (kc,d)
    float* St  = sm + 3 * 64 * 68;  // [64][68] (q,kc) scores -> probs

    int qt = blockIdx.x, h = blockIdx.y, b = blockIdx.z;
    int kh = h >> 2;   // GQA: 4 q heads per kv head
    int tid = threadIdx.x;

    // load Q tile (scaled by 1/sqrt(HD)=1/8)
    for (int i = tid; i < 1024; i += 256) {
        int r = i >> 4, c4 = (i & 15) << 2;
        const float* src = g_q + (((size_t)(b * SEQ + (qt << 6) + r) * NH + h) << 6) + c4;
        float4 qv = *(const float4*)src;
        float* dst = &Qt[r * 68 + c4];
        dst[0] = qv.x * 0.125f; dst[1] = qv.y * 0.125f;
        dst[2] = qv.z * 0.125f; dst[3] = qv.w * 0.125f;
    }

    int qr = tid >> 2, qc = tid & 3;     // softmax/PV mapping: row qr, dims qc*16..+16
    int pi = tid >> 4, pj = tid & 15;    // score mapping: 4x4 patch
    int qr0 = pi << 2, kc0 = pj << 2;

    float acc[16];
    #pragma unroll
    for (int d = 0; d < 16; d++) acc[d] = 0.0f;
    float mrow = -INFINITY, lrow = 0.0f;

    for (int kt = 0; kt <= qt; kt++) {
        __syncthreads();  // previous-tile phase C done before K/V overwrite
        int tokbase = b * SEQ + (kt << 6);
        // K transposed
        for (int i = tid; i < 1024; i += 256) {
            int r = i & 63, c4 = (i >> 6) << 2;
            const float* src = g_k + (((size_t)(tokbase + r) * NKV + kh) << 6) + c4;
            float4 kv = *(const float4*)src;
            KtT[(c4 + 0) * 68 + r] = kv.x;
            KtT[(c4 + 1) * 68 + r] = kv.y;
            KtT[(c4 + 2) * 68 + r] = kv.z;
            KtT[(c4 + 3) * 68 + r] = kv.w;
        }
        // V row-major
        for (int i = tid; i < 1024; i += 256) {
            int r = i >> 4, c4 = (i & 15) << 2;
            const float* src = g_v + (((size_t)(tokbase + r) * NKV + kh) << 6) + c4;
            *(float4*)&Vt[r * 68 + c4] = *(const float4*)src;
        }
        __syncthreads();

        // phase A: S = (Q/8) K^T  (4x4 patch per thread)
        float sacc[4][4];
        #pragma unroll
        for (int i = 0; i < 4; i++)
            #pragma unroll
            for (int j = 0; j < 4; j++) sacc[i][j] = 0.0f;
        #pragma unroll
        for (int d4 = 0; d4 < 64; d4 += 4) {
            float aq[4][4], bk[4][4];
            #pragma unroll
            for (int i = 0; i < 4; i++)
                *(float4*)aq[i] = *(const float4*)&Qt[(qr0 + i) * 68 + d4];
            #pragma unroll
            for (int dd = 0; dd < 4; dd++)
                *(float4*)bk[dd] = *(const float4*)&KtT[(d4 + dd) * 68 + kc0];
            #pragma unroll
            for (int i = 0; i < 4; i++)
                #pragma unroll
                for (int dd = 0; dd < 4; dd++)
                    #pragma unroll
                    for (int j = 0; j < 4; j++)
                        sacc[i][j] += aq[i][dd] * bk[dd][j];
        }
        // causal mask on diagonal tile, store scores
        bool diag = (kt == qt);
        #pragma unroll
        for (int i = 0; i < 4; i++) {
            int qg = (qt << 6) + qr0 + i;
            float4 r;
            float v0 = sacc[i][0], v1 = sacc[i][1], v2 = sacc[i][2], v3 = sacc[i][3];
            if (diag) {
                int kg = (kt << 6) + kc0;
                if (kg + 0 > qg) v0 = -INFINITY;
                if (kg + 1 > qg) v1 = -INFINITY;
                if (kg + 2 > qg) v2 = -INFINITY;
                if (kg + 3 > qg) v3 = -INFINITY;
            }
            r.x = v0; r.y = v1; r.z = v2; r.w = v3;
            *(float4*)&St[(qr0 + i) * 68 + kc0] = r;
        }
        __syncthreads();

        // phase B: online softmax (4 lanes per row)
        float* srow = &St[qr * 68 + (qc << 4)];
        float tmax = -INFINITY;
        #pragma unroll
        for (int j = 0; j < 16; j++) tmax = fmaxf(tmax, srow[j]);
        tmax = fmaxf(tmax, __shfl_xor_sync(0xffffffffu, tmax, 1));
        tmax = fmaxf(tmax, __shfl_xor_sync(0xffffffffu, tmax, 2));
        float mnew = fmaxf(mrow, tmax);
        float corr = __expf(mrow - mnew);
        float psum = 0.0f;
        #pragma unroll
        for (int j = 0; j < 16; j++) {
            float pv = __expf(srow[j] - mnew);
            srow[j] = pv;
            psum += pv;
        }
        psum += __shfl_xor_sync(0xffffffffu, psum, 1);
        psum += __shfl_xor_sync(0xffffffffu, psum, 2);
        lrow = lrow * corr + psum;
        mrow = mnew;
        #pragma unroll
        for (int d = 0; d < 16; d++) acc[d] *= corr;
        __syncwarp();  // sibling lanes' prob writes visible (same warp owns row qr)

        // phase C: acc += P V
        for (int kc = 0; kc < 64; kc++) {
            float pv = St[qr * 68 + kc];
            const float4 v0 = *(const float4*)&Vt[kc * 68 + (qc << 4) + 0];
            const float4 v1 = *(const float4*)&Vt[kc * 68 + (qc << 4) + 4];
            const float4 v2 = *(const float4*)&Vt[kc * 68 + (qc << 4) + 8];
            const float4 v3 = *(const float4*)&Vt[kc * 68 + (qc << 4) + 12];
            acc[0]  += pv * v0.x; acc[1]  += pv * v0.y; acc[2]  += pv * v0.z; acc[3]  += pv * v0.w;
            acc[4]  += pv * v1.x; acc[5]  += pv * v1.y; acc[6]  += pv * v1.z; acc[7]  += pv * v1.w;
            acc[8]  += pv * v2.x; acc[9]  += pv * v2.y; acc[10] += pv * v2.z; acc[11] += pv * v2.w;
            acc[12] += pv * v3.x; acc[13] += pv * v3.y; acc[14] += pv * v3.z; acc[15] += pv * v3.w;
        }
    }

    // epilogue: normalize, write back in-place over this block's Q region
    float inv_l = 1.0f / lrow;
    float* outp = g_q + (((size_t)(b * SEQ + (qt << 6) + qr) * NH + h) << 6) + (qc << 4);
    #pragma unroll
    for (int d = 0; d < 16; d += 4) {
        float4 o;
        o.x = acc[d + 0] * inv_l;
        o.y = acc[d + 1] * inv_l;
        o.z = acc[d + 2] * inv_l;
        o.w = acc[d + 3] * inv_l;
        *(float4*)&outp[d] = o;
    }
}

// ---------------- launch ----------------
extern "C" void kernel_launch(void* const* d_in, const int* in_sizes, int n_in,
                              void* d_out, int out_size) {
    (void)in_sizes; (void)n_in; (void)out_size;
    const float* hs     = (const float*)d_in[0];
    const int*   pos    = (const int*)d_in[2];
    const float* q_w    = (const float*)d_in[3];
    const float* k_w    = (const float*)d_in[4];
    const float* v_w    = (const float*)d_in[5];
    const float* o_w    = (const float*)d_in[6];
    const float* gate_w = (const float*)d_in[7];
    const float* up_w   = (const float*)d_in[8];
    const float* down_w = (const float*)d_in[9];
    const float* ln1    = (const float*)d_in[10];
    const float* ln2    = (const float*)d_in[11];
    const float* kkp    = (const float*)d_in[12];
    const float* aap    = (const float*)d_in[13];
    float* out = (float*)d_out;

    float *xn, *q, *k, *v, *hid, *gate;
    cudaGetSymbolAddress((void**)&xn,   g_xn);
    cudaGetSymbolAddress((void**)&q,    g_q);
    cudaGetSymbolAddress((void**)&k,    g_k);
    cudaGetSymbolAddress((void**)&v,    g_v);
    cudaGetSymbolAddress((void**)&hid,  g_hidden);
    cudaGetSymbolAddress((void**)&gate, g_gate);

    cudaFuncSetAttribute(attn_kernel, cudaFuncAttributeMaxDynamicSharedMemorySize, ATTN_SMEM);

    dim3 blk(256);

    // 1) rmsnorm 1
    rmsnorm_kernel<<<M_TOK, blk>>>(hs, ln1, xn);
    // 2) q/k/v projections
    gemm_binlin<0><<<dim3(H / 128, M_TOK / 128), blk>>>(xn, q_w, nullptr, q, H, H, kkp, aap);
    gemm_binlin<0><<<dim3((NKV * HD) / 128, M_TOK / 128), blk>>>(xn, k_w, nullptr, k, NKV * HD, H, kkp, aap);
    gemm_binlin<0><<<dim3((NKV * HD) / 128, M_TOK / 128), blk>>>(xn, v_w, nullptr, v, NKV * HD, H, kkp, aap);
    // 3) rope on q and k
    rope_kernel<<<(M_TOK * (NH + NKV) * 32) / 256, blk>>>(pos);
    // 4) attention (writes into g_q)
    attn_kernel<<<dim3(SEQ / 64, NH, BATCH), blk, ATTN_SMEM>>>();
    // 5) o-proj + residual
    gemm_binlin<1><<<dim3(H / 128, M_TOK / 128), blk>>>(q, o_w, hs, hid, H, H, kkp, aap);
    // 6) rmsnorm 2
    rmsnorm_kernel<<<M_TOK, blk>>>(hid, ln2, xn);
    // 7) gate proj
    gemm_binlin<0><<<dim3(FF / 128, M_TOK / 128), blk>>>(xn, gate_w, nullptr, gate, FF, H, kkp, aap);
    // 8) up proj fused with silu(gate)*up  (in-place into gate buffer)
    gemm_binlin<2><<<dim3(FF / 128, M_TOK / 128), blk>>>(xn, up_w, gate, gate, FF, H, kkp, aap);
    // 9) down proj + residual -> output
    gemm_binlin<1><<<dim3(H / 128, M_TOK / 128), blk>>>(gate, down_w, hid, out, H, FF, kkp, aap);
}

// round 3
// speedup vs baseline: 1.5780x; 1.5780x over previous
#include <cuda_runtime.h>
#include <cuda_bf16.h>
#include <math.h>

#define H      2048
#define NH     32
#define NKV    8
#define HD     64
#define GROUPS 4
#define FF     5632
#define BATCH  2
#define SEQ    2048
#define M_TOK  (BATCH*SEQ)

#define ATTN_SMEM (4*64*68*4)

// weight plane element offsets
#define OFF_Q  ((size_t)0)
#define OFF_K  (OFF_Q + (size_t)2048*2048)
#define OFF_V  (OFF_K + (size_t)512*2048)
#define OFF_O  (OFF_V + (size_t)512*2048)
#define OFF_G  (OFF_O + (size_t)2048*2048)
#define OFF_U  (OFF_G + (size_t)5632*2048)
#define OFF_D  (OFF_U + (size_t)5632*2048)
#define W_TOTAL (OFF_D + (size_t)2048*5632)

// ---------------- scratch (device globals: allocation-guard safe) ----------------
__device__ float g_q[M_TOK*H];
__device__ float g_k[M_TOK*NKV*HD];
__device__ float g_v[M_TOK*NKV*HD];
__device__ float g_hidden[M_TOK*H];
__device__ float g_gate[M_TOK*FF];
__device__ __nv_bfloat16 g_xn_h[M_TOK*H];
__device__ __nv_bfloat16 g_xn_l[M_TOK*H];
__device__ __nv_bfloat16 g_ao_h[M_TOK*H];
__device__ __nv_bfloat16 g_ao_l[M_TOK*H];
__device__ __nv_bfloat16 g_act_h[M_TOK*FF];
__device__ __nv_bfloat16 g_act_l[M_TOK*FF];
__device__ __nv_bfloat16 g_w_h[W_TOTAL];
__device__ __nv_bfloat16 g_w_l[W_TOTAL];

// ---------------- helpers ----------------
__device__ __forceinline__ unsigned pack_bf2(float a, float b) {
    __nv_bfloat162 t = __floats2bfloat162_rn(a, b);
    return *(unsigned*)&t;
}
__device__ __forceinline__ void split1(float x, float& hi, float& lo) {
    __nv_bfloat16 hb = __float2bfloat16(x);
    hi = __bfloat162float(hb);
    lo = x - hi;
}

// ---------------- weight binarize + bf16 hi/lo split prepass ----------------
__global__ void binsplit_kernel(const float* __restrict__ src,
                                __nv_bfloat16* __restrict__ dh,
                                __nv_bfloat16* __restrict__ dl,
                                const float* __restrict__ kkp, const float* __restrict__ aap) {
    const float kk = kkp[0], aa = aap[0];
    size_t i = ((size_t)blockIdx.x * 256 + threadIdx.x) * 4;
    float4 w = *(const float4*)(src + i);
    float v[4] = {w.x, w.y, w.z, w.w};
    float hv[4], lv[4];
    #pragma unroll
    for (int j = 0; j < 4; j++) {
        float b = aa * fminf(fmaxf(kk * v[j], -1.0f), 1.0f);
        split1(b, hv[j], lv[j]);
    }
    uint2 ph = {pack_bf2(hv[0], hv[1]), pack_bf2(hv[2], hv[3])};
    uint2 pl = {pack_bf2(lv[0], lv[1]), pack_bf2(lv[2], lv[3])};
    *(uint2*)(dh + i) = ph;
    *(uint2*)(dl + i) = pl;
}

// ---------------- RMSNorm -> bf16 hi/lo planes ----------------
__global__ void rmsnorm_kernel(const float* __restrict__ x, const float* __restrict__ w,
                               __nv_bfloat16* __restrict__ yh, __nv_bfloat16* __restrict__ yl) {
    int row = blockIdx.x;
    const float4* xr = (const float4*)(x + (size_t)row * H);
    const float4* wv = (const float4*)w;
    int tid = threadIdx.x;
    float4 a = xr[tid];
    float4 b = xr[tid + 256];
    float ss = a.x*a.x + a.y*a.y + a.z*a.z + a.w*a.w
             + b.x*b.x + b.y*b.y + b.z*b.z + b.w*b.w;
    #pragma unroll
    for (int o = 16; o; o >>= 1) ss += __shfl_xor_sync(0xffffffffu, ss, o);
    __shared__ float ws[8];
    if ((tid & 31) == 0) ws[tid >> 5] = ss;
    __syncthreads();
    float tot = ws[0]+ws[1]+ws[2]+ws[3]+ws[4]+ws[5]+ws[6]+ws[7];
    float r = rsqrtf(tot * (1.0f / (float)H) + 1e-5f);
    float4 w0 = wv[tid], w1 = wv[tid + 256];
    float o0[4] = {a.x*r*w0.x, a.y*r*w0.y, a.z*r*w0.z, a.w*r*w0.w};
    float o1[4] = {b.x*r*w1.x, b.y*r*w1.y, b.z*r*w1.z, b.w*r*w1.w};
    float h0[4], l0[4], h1[4], l1[4];
    #pragma unroll
    for (int j = 0; j < 4; j++) { split1(o0[j], h0[j], l0[j]); split1(o1[j], h1[j], l1[j]); }
    size_t base = (size_t)row * H + 4 * tid;
    *(uint2*)(yh + base)        = make_uint2(pack_bf2(h0[0],h0[1]), pack_bf2(h0[2],h0[3]));
    *(uint2*)(yl + base)        = make_uint2(pack_bf2(l0[0],l0[1]), pack_bf2(l0[2],l0[3]));
    *(uint2*)(yh + base + 1024) = make_uint2(pack_bf2(h1[0],h1[1]), pack_bf2(h1[2],h1[3]));
    *(uint2*)(yl + base + 1024) = make_uint2(pack_bf2(l1[0],l1[1]), pack_bf2(l1[2],l1[3]));
}

// ---------------- tensor-core GEMM (bf16 split, mma.sync m16n8k16) ----------------
// C[M,N] = A @ W^T where A = Ah+Al, W = Wh+Wl (bf16 planes), via 3 MMA passes.
// MODE 0: C fp32 store. MODE 1: C = acc + X (fp32). MODE 2: silu(X)*acc -> (Ch,Cl) bf16 planes.
#define MMA_B16(c, a, b) \
    asm volatile("mma.sync.aligned.m16n8k16.row.col.f32.bf16.bf16.f32 " \
                 "{%0,%1,%2,%3},{%4,%5,%6,%7},{%8,%9},{%0,%1,%2,%3};" \
                 : "+f"(c[0]), "+f"(c[1]), "+f"(c[2]), "+f"(c[3]) \
                 : "r"(a[0]), "r"(a[1]), "r"(a[2]), "r"(a[3]), "r"(b[0]), "r"(b[1]))

template<int MODE>
__global__ void __launch_bounds__(256) gemm_mma(
    const __nv_bfloat16* __restrict__ Ah, const __nv_bfloat16* __restrict__ Al,
    const __nv_bfloat16* __restrict__ Wh, const __nv_bfloat16* __restrict__ Wl,
    const float* __restrict__ X, float* __restrict__ C,
    __nv_bfloat16* __restrict__ Ch, __nv_bfloat16* __restrict__ Cl,
    int N, int K)
{
    // 4 planes (Ah, Al, Wh, Wl), 128 rows x 16 bf16, row stride 48B, double buffered
    __shared__ __align__(16) unsigned char sm[2][4][128 * 48];

    int tid = threadIdx.x;
    int bm = blockIdx.y << 7;
    int bn = blockIdx.x << 7;

    // staging mapping: thread -> (row, half) ; 8 bf16 (16B) per plane per thread
    int srow = tid >> 1, shalf = tid & 1;
    const __nv_bfloat16* pAh = Ah + (size_t)(bm + srow) * K + shalf * 8;
    const __nv_bfloat16* pAl = Al + (size_t)(bm + srow) * K + shalf * 8;
    const __nv_bfloat16* pWh = Wh + (size_t)(bn + srow) * K + shalf * 8;
    const __nv_bfloat16* pWl = Wl + (size_t)(bn + srow) * K + shalf * 8;
    int sOff = srow * 48 + shalf * 16;

    // compute mapping
    int warp = tid >> 5, lane = tid & 31;
    int m0 = (warp & 1) << 6;     // 0 or 64
    int n0 = (warp >> 1) << 5;    // 0,32,64,96
    int fr = lane >> 2, kp = lane & 3;
    int aBase = (m0 + fr) * 48 + kp * 4;
    int bBase = (n0 + fr) * 48 + kp * 4;

    float acc[4][4][4];
    #pragma unroll
    for (int i = 0; i < 4; i++)
        #pragma unroll
        for (int j = 0; j < 4; j++)
            #pragma unroll
            for (int r = 0; r < 4; r++) acc[i][j][r] = 0.0f;

    int nk = K >> 4;

    uint4 rAh = *(const uint4*)pAh;
    uint4 rAl = *(const uint4*)pAl;
    uint4 rWh = *(const uint4*)pWh;
    uint4 rWl = *(const uint4*)pWl;
    *(uint4*)(sm[0][0] + sOff) = rAh;
    *(uint4*)(sm[0][1] + sOff) = rAl;
    *(uint4*)(sm[0][2] + sOff) = rWh;
    *(uint4*)(sm[0][3] + sOff) = rWl;
    __syncthreads();

    for (int kb = 0; kb < nk; kb++) {
        int cur = kb & 1, nxt = cur ^ 1;
        if (kb + 1 < nk) {
            int ko = (kb + 1) << 4;
            rAh = *(const uint4*)(pAh + ko);
            rAl = *(const uint4*)(pAl + ko);
            rWh = *(const uint4*)(pWh + ko);
            rWl = *(const uint4*)(pWl + ko);
        }

        const unsigned char* sAh = sm[cur][0];
        const unsigned char* sAl = sm[cur][1];
        const unsigned char* sWh = sm[cur][2];
        const unsigned char* sWl = sm[cur][3];

        unsigned aH[4][4], aL[4][4], bH[4][2], bL[4][2];
        #pragma unroll
        for (int i = 0; i < 4; i++) {
            int off = aBase + i * 768;   // 16*48
            aH[i][0] = *(const unsigned*)(sAh + off);
            aH[i][1] = *(const unsigned*)(sAh + off + 384);   // +8 rows
            aH[i][2] = *(const unsigned*)(sAh + off + 16);    // +8 k
            aH[i][3] = *(const unsigned*)(sAh + off + 400);
            aL[i][0] = *(const unsigned*)(sAl + off);
            aL[i][1] = *(const unsigned*)(sAl + off + 384);
            aL[i][2] = *(const unsigned*)(sAl + off + 16);
            aL[i][3] = *(const unsigned*)(sAl + off + 400);
        }
        #pragma unroll
        for (int j = 0; j < 4; j++) {
            int off = bBase + j * 384;   // 8*48
            bH[j][0] = *(const unsigned*)(sWh + off);
            bH[j][1] = *(const unsigned*)(sWh + off + 16);
            bL[j][0] = *(const unsigned*)(sWl + off);
            bL[j][1] = *(const unsigned*)(sWl + off + 16);
        }

        #pragma unroll
        for (int i = 0; i < 4; i++)
            #pragma unroll
            for (int j = 0; j < 4; j++) MMA_B16(acc[i][j], aH[i], bH[j]);
        #pragma unroll
        for (int i = 0; i < 4; i++)
            #pragma unroll
            for (int j = 0; j < 4; j++) MMA_B16(acc[i][j], aH[i], bL[j]);
        #pragma unroll
        for (int i = 0; i < 4; i++)
            #pragma unroll
            for (int j = 0; j < 4; j++) MMA_B16(acc[i][j], aL[i], bH[j]);

        if (kb + 1 < nk) {
            *(uint4*)(sm[nxt][0] + sOff) = rAh;
            *(uint4*)(sm[nxt][1] + sOff) = rAl;
            *(uint4*)(sm[nxt][2] + sOff) = rWh;
            *(uint4*)(sm[nxt][3] + sOff) = rWl;
        }
        __syncthreads();
    }

    // epilogue
    #pragma unroll
    for (int i = 0; i < 4; i++) {
        #pragma unroll
        for (int j = 0; j < 4; j++) {
            int row0 = bm + m0 + 16 * i + fr;
            int col  = bn + n0 + 8 * j + kp * 2;
            #pragma unroll
            for (int half = 0; half < 2; half++) {
                int row = row0 + half * 8;
                float v0 = acc[i][j][2 * half + 0];
                float v1 = acc[i][j][2 * half + 1];
                size_t off = (size_t)row * N + col;
                if (MODE == 0) {
                    *(float2*)(C + off) = make_float2(v0, v1);
                } else if (MODE == 1) {
                    float2 xr = *(const float2*)(X + off);
                    *(float2*)(C + off) = make_float2(v0 + xr.x, v1 + xr.y);
                } else {
                    float2 gr = *(const float2*)(X + off);
                    v0 *= gr.x / (1.0f + expf(-gr.x));
                    v1 *= gr.y / (1.0f + expf(-gr.y));
                    float h0, l0, h1, l1;
                    split1(v0, h0, l0);
                    split1(v1, h1, l1);
                    *(unsigned*)(Ch + off) = pack_bf2(h0, h1);
                    *(unsigned*)(Cl + off) = pack_bf2(l0, l1);
                }
            }
        }
    }
}

// ---------------- RoPE (in-place on g_q and g_k) ----------------
__global__ void rope_kernel(const int* __restrict__ pos_ids) {
    int gid = blockIdx.x * blockDim.x + threadIdx.x;
    int d = gid & 31;
    int slot = gid >> 5;
    int head = slot % (NH + NKV);
    int tok = slot / (NH + NKV);
    if (tok >= M_TOK) return;
    float p = (float)pos_ids[tok];
    float inv = powf(10000.0f, -(float)d * (1.0f / 32.0f));
    float ang = p * inv;
    float s, c;
    sincosf(ang, &s, &c);
    float* base;
    if (head < NH) base = g_q + (((size_t)tok * NH + head) << 6);
    else           base = g_k + (((size_t)tok * NKV + (head - NH)) << 6);
    float x1 = base[d];
    float x2 = base[d + 32];
    base[d]      = x1 * c - x2 * s;
    base[d + 32] = x2 * c + x1 * s;
}

// ---------------- Flash attention (causal, GQA) -> bf16 hi/lo planes ----------------
__global__ void __launch_bounds__(256, 1) attn_kernel() {
    extern __shared__ float sm[];
    float* Qt  = sm;
    float* KtT = sm + 64 * 68;
    float* Vt  = sm + 2 * 64 * 68;
    float* St  = sm + 3 * 64 * 68;

    int qt = blockIdx.x, h = blockIdx.y, b = blockIdx.z;
    int kh = h >> 2;
    int tid = threadIdx.x;

    for (int i = tid; i < 1024; i += 256) {
        int r = i >> 4, c4 = (i & 15) << 2;
        const float* src = g_q + (((size_t)(b * SEQ + (qt << 6) + r) * NH + h) << 6) + c4;
        float4 qv = *(const float4*)src;
        float* dst = &Qt[r * 68 + c4];
        dst[0] = qv.x * 0.125f; dst[1] = qv.y * 0.125f;
        dst[2] = qv.z * 0.125f; dst[3] = qv.w * 0.125f;
    }

    int qr = tid >> 2, qc = tid & 3;
    int pi = tid >> 4, pj = tid & 15;
    int qr0 = pi << 2, kc0 = pj << 2;

    float acc[16];
    #pragma unroll
    for (int d = 0; d < 16; d++) acc[d] = 0.0f;
    float mrow = -INFINITY, lrow = 0.0f;

    for (int kt = 0; kt <= qt; kt++) {
        __syncthreads();
        int tokbase = b * SEQ + (kt << 6);
        for (int i = tid; i < 1024; i += 256) {
            int r = i & 63, c4 = (i >> 6) << 2;
            const float* src = g_k + (((size_t)(tokbase + r) * NKV + kh) << 6) + c4;
            float4 kv = *(const float4*)src;
            KtT[(c4 + 0) * 68 + r] = kv.x;
            KtT[(c4 + 1) * 68 + r] = kv.y;
            KtT[(c4 + 2) * 68 + r] = kv.z;
            KtT[(c4 + 3) * 68 + r] = kv.w;
        }
        for (int i = tid; i < 1024; i += 256) {
            int r = i >> 4, c4 = (i & 15) << 2;
            const float* src = g_v + (((size_t)(tokbase + r) * NKV + kh) << 6) + c4;
            *(float4*)&Vt[r * 68 + c4] = *(const float4*)src;
        }
        __syncthreads();

        float sacc[4][4];
        #pragma unroll
        for (int i = 0; i < 4; i++)
            #pragma unroll
            for (int j = 0; j < 4; j++) sacc[i][j] = 0.0f;
        #pragma unroll
        for (int d4 = 0; d4 < 64; d4 += 4) {
            float aq[4][4], bk[4][4];
            #pragma unroll
            for (int i = 0; i < 4; i++)
                *(float4*)aq[i] = *(const float4*)&Qt[(qr0 + i) * 68 + d4];
            #pragma unroll
            for (int dd = 0; dd < 4; dd++)
                *(float4*)bk[dd] = *(const float4*)&KtT[(d4 + dd) * 68 + kc0];
            #pragma unroll
            for (int i = 0; i < 4; i++)
                #pragma unroll
                for (int dd = 0; dd < 4; dd++)
                    #pragma unroll
                    for (int j = 0; j < 4; j++)
                        sacc[i][j] += aq[i][dd] * bk[dd][j];
        }
        bool diag = (kt == qt);
        #pragma unroll
        for (int i = 0; i < 4; i++) {
            int qg = (qt << 6) + qr0 + i;
            float4 r;
            float v0 = sacc[i][0], v1 = sacc[i][1], v2 = sacc[i][2], v3 = sacc[i][3];
            if (diag) {
                int kg = (kt << 6) + kc0;
                if (kg + 0 > qg) v0 = -INFINITY;
                if (kg + 1 > qg) v1 = -INFINITY;
                if (kg + 2 > qg) v2 = -INFINITY;
                if (kg + 3 > qg) v3 = -INFINITY;
            }
            r.x = v0; r.y = v1; r.z = v2; r.w = v3;
            *(float4*)&St[(qr0 + i) * 68 + kc0] = r;
        }
        __syncthreads();

        float* srow = &St[qr * 68 + (qc << 4)];
        float tmax = -INFINITY;
        #pragma unroll
        for (int j = 0; j < 16; j++) tmax = fmaxf(tmax, srow[j]);
        tmax = fmaxf(tmax, __shfl_xor_sync(0xffffffffu, tmax, 1));
        tmax = fmaxf(tmax, __shfl_xor_sync(0xffffffffu, tmax, 2));
        float mnew = fmaxf(mrow, tmax);
        float corr = __expf(mrow - mnew);
        float psum = 0.0f;
        #pragma unroll
        for (int j = 0; j < 16; j++) {
            float pv = __expf(srow[j] - mnew);
            srow[j] = pv;
            psum += pv;
        }
        psum += __shfl_xor_sync(0xffffffffu, psum, 1);
        psum += __shfl_xor_sync(0xffffffffu, psum, 2);
        lrow = lrow * corr + psum;
        mrow = mnew;
        #pragma unroll
        for (int d = 0; d < 16; d++) acc[d] *= corr;
        __syncwarp();

        for (int kc = 0; kc < 64; kc++) {
            float pv = St[qr * 68 + kc];
            const float4 v0 = *(const float4*)&Vt[kc * 68 + (qc << 4) + 0];
            const float4 v1 = *(const float4*)&Vt[kc * 68 + (qc << 4) + 4];
            const float4 v2 = *(const float4*)&Vt[kc * 68 + (qc << 4) + 8];
            const float4 v3 = *(const float4*)&Vt[kc * 68 + (qc << 4) + 12];
            acc[0]  += pv * v0.x; acc[1]  += pv * v0.y; acc[2]  += pv * v0.z; acc[3]  += pv * v0.w;
            acc[4]  += pv * v1.x; acc[5]  += pv * v1.y; acc[6]  += pv * v1.z; acc[7]  += pv * v1.w;
            acc[8]  += pv * v2.x; acc[9]  += pv * v2.y; acc[10] += pv * v2.z; acc[11] += pv * v2.w;
            acc[12] += pv * v3.x; acc[13] += pv * v3.y; acc[14] += pv * v3.z; acc[15] += pv * v3.w;
        }
    }

    // epilogue: normalize + bf16 hi/lo split -> planes for o-proj
    float inv_l = 1.0f / lrow;
    float o[16], oh[16], ol[16];
    #pragma unroll
    for (int d = 0; d < 16; d++) {
        o[d] = acc[d] * inv_l;
        split1(o[d], oh[d], ol[d]);
    }
    size_t idx = (((size_t)(b * SEQ + (qt << 6) + qr) * NH + h) << 6) + (qc << 4);
    uint4 ph0 = make_uint4(pack_bf2(oh[0],oh[1]), pack_bf2(oh[2],oh[3]),
                           pack_bf2(oh[4],oh[5]), pack_bf2(oh[6],oh[7]));
    uint4 ph1 = make_uint4(pack_bf2(oh[8],oh[9]), pack_bf2(oh[10],oh[11]),
                           pack_bf2(oh[12],oh[13]), pack_bf2(oh[14],oh[15]));
    uint4 pl0 = make_uint4(pack_bf2(ol[0],ol[1]), pack_bf2(ol[2],ol[3]),
                           pack_bf2(ol[4],ol[5]), pack_bf2(ol[6],ol[7]));
    uint4 pl1 = make_uint4(pack_bf2(ol[8],ol[9]), pack_bf2(ol[10],ol[11]),
                           pack_bf2(ol[12],ol[13]), pack_bf2(ol[14],ol[15]));
    *(uint4*)(g_ao_h + idx)     = ph0;
    *(uint4*)(g_ao_h + idx + 8) = ph1;
    *(uint4*)(g_ao_l + idx)     = pl0;
    *(uint4*)(g_ao_l + idx + 8) = pl1;
}

// ---------------- launch ----------------
extern "C" void kernel_launch(void* const* d_in, const int* in_sizes, int n_in,
                              void* d_out, int out_size) {
    (void)in_sizes; (void)n_in; (void)out_size;
    const float* hs     = (const float*)d_in[0];
    const int*   pos    = (const int*)d_in[2];
    const float* q_w    = (const float*)d_in[3];
    const float* k_w    = (const float*)d_in[4];
    const float* v_w    = (const float*)d_in[5];
    const float* o_w    = (const float*)d_in[6];
    const float* gate_w = (const float*)d_in[7];
    const float* up_w   = (const float*)d_in[8];
    const float* down_w = (const float*)d_in[9];
    const float* ln1    = (const float*)d_in[10];
    const float* ln2    = (const float*)d_in[11];
    const float* kkp    = (const float*)d_in[12];
    const float* aap    = (const float*)d_in[13];
    float* out = (float*)d_out;

    float *q, *k, *v, *hid, *gate;
    __nv_bfloat16 *xnh, *xnl, *aoh, *aol, *acth, *actl, *wh, *wl;
    cudaGetSymbolAddress((void**)&q,    g_q);
    cudaGetSymbolAddress((void**)&k,    g_k);
    cudaGetSymbolAddress((void**)&v,    g_v);
    cudaGetSymbolAddress((void**)&hid,  g_hidden);
    cudaGetSymbolAddress((void**)&gate, g_gate);
    cudaGetSymbolAddress((void**)&xnh,  g_xn_h);
    cudaGetSymbolAddress((void**)&xnl,  g_xn_l);
    cudaGetSymbolAddress((void**)&aoh,  g_ao_h);
    cudaGetSymbolAddress((void**)&aol,  g_ao_l);
    cudaGetSymbolAddress((void**)&acth, g_act_h);
    cudaGetSymbolAddress((void**)&actl, g_act_l);
    cudaGetSymbolAddress((void**)&wh,   g_w_h);
    cudaGetSymbolAddress((void**)&wl,   g_w_l);

    cudaFuncSetAttribute(attn_kernel, cudaFuncAttributeMaxDynamicSharedMemorySize, ATTN_SMEM);

    dim3 blk(256);

    // 0) weight prepass: binarize + bf16 split
    binsplit_kernel<<<(2048*2048)/1024, blk>>>(q_w,    wh + OFF_Q, wl + OFF_Q, kkp, aap);
    binsplit_kernel<<<(512*2048)/1024,  blk>>>(k_w,    wh + OFF_K, wl + OFF_K, kkp, aap);
    binsplit_kernel<<<(512*2048)/1024,  blk>>>(v_w,    wh + OFF_V, wl + OFF_V, kkp, aap);
    binsplit_kernel<<<(2048*2048)/1024, blk>>>(o_w,    wh + OFF_O, wl + OFF_O, kkp, aap);
    binsplit_kernel<<<(5632*2048)/1024, blk>>>(gate_w, wh + OFF_G, wl + OFF_G, kkp, aap);
    binsplit_kernel<<<(5632*2048)/1024, blk>>>(up_w,   wh + OFF_U, wl + OFF_U, kkp, aap);
    binsplit_kernel<<<(2048*5632)/1024, blk>>>(down_w, wh + OFF_D, wl + OFF_D, kkp, aap);

    // 1) rmsnorm 1 -> planes
    rmsnorm_kernel<<<M_TOK, blk>>>(hs, ln1, xnh, xnl);
    // 2) q/k/v projections
    gemm_mma<0><<<dim3(H/128, M_TOK/128), blk>>>(xnh, xnl, wh+OFF_Q, wl+OFF_Q, nullptr, q, nullptr, nullptr, H, H);
    gemm_mma<0><<<dim3((NKV*HD)/128, M_TOK/128), blk>>>(xnh, xnl, wh+OFF_K, wl+OFF_K, nullptr, k, nullptr, nullptr, NKV*HD, H);
    gemm_mma<0><<<dim3((NKV*HD)/128, M_TOK/128), blk>>>(xnh, xnl, wh+OFF_V, wl+OFF_V, nullptr, v, nullptr, nullptr, NKV*HD, H);
    // 3) rope
    rope_kernel<<<(M_TOK*(NH+NKV)*32)/256, blk>>>(pos);
    // 4) attention -> ao planes
    attn_kernel<<<dim3(SEQ/64, NH, BATCH), blk, ATTN_SMEM>>>();
    // 5) o-proj + residual
    gemm_mma<1><<<dim3(H/128, M_TOK/128), blk>>>(aoh, aol, wh+OFF_O, wl+OFF_O, hs, hid, nullptr, nullptr, H, H);
    // 6) rmsnorm 2 -> planes
    rmsnorm_kernel<<<M_TOK, blk>>>(hid, ln2, xnh, xnl);
    // 7) gate proj (fp32 out)
    gemm_mma<0><<<dim3(FF/128, M_TOK/128), blk>>>(xnh, xnl, wh+OFF_G, wl+OFF_G, nullptr, gate, nullptr, nullptr, FF, H);
    // 8) up proj, fused silu(gate)*up -> act planes
    gemm_mma<2><<<dim3(FF/128, M_TOK/128), blk>>>(xnh, xnl, wh+OFF_U, wl+OFF_U, gate, nullptr, acth, actl, FF, H);
    // 9) down proj + residual -> out
    gemm_mma<1><<<dim3(H/128, M_TOK/128), blk>>>(acth, actl, wh+OFF_D, wl+OFF_D, hid, out, nullptr, nullptr, H, FF);
}

// round 4
// speedup vs baseline: 1.9891x; 1.2605x over previous
#include <cuda_runtime.h>
#include <cuda_bf16.h>
#include <math.h>

#define H      2048
#define NH     32
#define NKV    8
#define HD     64
#define GROUPS 4
#define FF     5632
#define BATCH  2
#define SEQ    2048
#define M_TOK  (BATCH*SEQ)

#define ATTN_SMEM (4*64*68*4)
#define GEMM_SMEM 65536

// weight plane element offsets
#define OFF_Q  ((size_t)0)
#define OFF_K  (OFF_Q + (size_t)2048*2048)
#define OFF_V  (OFF_K + (size_t)512*2048)
#define OFF_O  (OFF_V + (size_t)512*2048)
#define OFF_G  (OFF_O + (size_t)2048*2048)
#define OFF_U  (OFF_G + (size_t)5632*2048)
#define OFF_D  (OFF_U + (size_t)5632*2048)
#define W_TOTAL (OFF_D + (size_t)2048*5632)

// ---------------- scratch (device globals: allocation-guard safe) ----------------
__device__ float g_q[M_TOK*H];
__device__ float g_k[M_TOK*NKV*HD];
__device__ float g_v[M_TOK*NKV*HD];
__device__ float g_hidden[M_TOK*H];
__device__ float g_gate[M_TOK*FF];
__device__ __nv_bfloat16 g_xn_h[M_TOK*H];
__device__ __nv_bfloat16 g_xn_l[M_TOK*H];
__device__ __nv_bfloat16 g_ao_h[M_TOK*H];
__device__ __nv_bfloat16 g_ao_l[M_TOK*H];
__device__ __nv_bfloat16 g_act_h[M_TOK*FF];
__device__ __nv_bfloat16 g_act_l[M_TOK*FF];
__device__ __nv_bfloat16 g_w_h[W_TOTAL];
__device__ __nv_bfloat16 g_w_l[W_TOTAL];

// ---------------- helpers ----------------
__device__ __forceinline__ unsigned pack_bf2(float a, float b) {
    __nv_bfloat162 t = __floats2bfloat162_rn(a, b);
    return *(unsigned*)&t;
}
__device__ __forceinline__ void split1(float x, float& hi, float& lo) {
    __nv_bfloat16 hb = __float2bfloat16(x);
    hi = __bfloat162float(hb);
    lo = x - hi;
}

#define SW64(x) ((unsigned)(x) ^ ((((unsigned)(x)) >> 3) & 0x30u))

#define CPA16(dst, src) \
    asm volatile("cp.async.cg.shared.global [%0], [%1], 16;" :: "r"(dst), "l"(src))
#define CPCOMMIT() asm volatile("cp.async.commit_group;")
#define CPWAIT0()  asm volatile("cp.async.wait_group 0;")

#define LDSM4(r, a) \
    asm volatile("ldmatrix.sync.aligned.m8n8.x4.shared.b16 {%0,%1,%2,%3}, [%4];" \
                 : "=r"((r)[0]), "=r"((r)[1]), "=r"((r)[2]), "=r"((r)[3]) : "r"(a))

#define MMA_B16(c, a, b0v, b1v) \
    asm volatile("mma.sync.aligned.m16n8k16.row.col.f32.bf16.bf16.f32 " \
                 "{%0,%1,%2,%3},{%4,%5,%6,%7},{%8,%9},{%0,%1,%2,%3};" \
                 : "+f"((c)[0]), "+f"((c)[1]), "+f"((c)[2]), "+f"((c)[3]) \
                 : "r"((a)[0]), "r"((a)[1]), "r"((a)[2]), "r"((a)[3]), "r"(b0v), "r"(b1v))

// ---------------- weight binarize + bf16 hi/lo split prepass ----------------
__global__ void binsplit_kernel(const float* __restrict__ src,
                                __nv_bfloat16* __restrict__ dh,
                                __nv_bfloat16* __restrict__ dl,
                                const float* __restrict__ kkp, const float* __restrict__ aap) {
    const float kk = kkp[0], aa = aap[0];
    size_t i = ((size_t)blockIdx.x * 256 + threadIdx.x) * 4;
    float4 w = *(const float4*)(src + i);
    float v[4] = {w.x, w.y, w.z, w.w};
    float hv[4], lv[4];
    #pragma unroll
    for (int j = 0; j < 4; j++) {
        float b = aa * fminf(fmaxf(kk * v[j], -1.0f), 1.0f);
        split1(b, hv[j], lv[j]);
    }
    uint2 ph = {pack_bf2(hv[0], hv[1]), pack_bf2(hv[2], hv[3])};
    uint2 pl = {pack_bf2(lv[0], lv[1]), pack_bf2(lv[2], lv[3])};
    *(uint2*)(dh + i) = ph;
    *(uint2*)(dl + i) = pl;
}

// ---------------- RMSNorm -> bf16 hi/lo planes ----------------
__global__ void rmsnorm_kernel(const float* __restrict__ x, const float* __restrict__ w,
                               __nv_bfloat16* __restrict__ yh, __nv_bfloat16* __restrict__ yl) {
    int row = blockIdx.x;
    const float4* xr = (const float4*)(x + (size_t)row * H);
    const float4* wv = (const float4*)w;
    int tid = threadIdx.x;
    float4 a = xr[tid];
    float4 b = xr[tid + 256];
    float ss = a.x*a.x + a.y*a.y + a.z*a.z + a.w*a.w
             + b.x*b.x + b.y*b.y + b.z*b.z + b.w*b.w;
    #pragma unroll
    for (int o = 16; o; o >>= 1) ss += __shfl_xor_sync(0xffffffffu, ss, o);
    __shared__ float ws[8];
    if ((tid & 31) == 0) ws[tid >> 5] = ss;
    __syncthreads();
    float tot = ws[0]+ws[1]+ws[2]+ws[3]+ws[4]+ws[5]+ws[6]+ws[7];
    float r = rsqrtf(tot * (1.0f / (float)H) + 1e-5f);
    float4 w0 = wv[tid], w1 = wv[tid + 256];
    float o0[4] = {a.x*r*w0.x, a.y*r*w0.y, a.z*r*w0.z, a.w*r*w0.w};
    float o1[4] = {b.x*r*w1.x, b.y*r*w1.y, b.z*r*w1.z, b.w*r*w1.w};
    float h0[4], l0[4], h1[4], l1[4];
    #pragma unroll
    for (int j = 0; j < 4; j++) { split1(o0[j], h0[j], l0[j]); split1(o1[j], h1[j], l1[j]); }
    size_t base = (size_t)row * H + 4 * tid;
    *(uint2*)(yh + base)        = make_uint2(pack_bf2(h0[0],h0[1]), pack_bf2(h0[2],h0[3]));
    *(uint2*)(yl + base)        = make_uint2(pack_bf2(l0[0],l0[1]), pack_bf2(l0[2],l0[3]));
    *(uint2*)(yh + base + 1024) = make_uint2(pack_bf2(h1[0],h1[1]), pack_bf2(h1[2],h1[3]));
    *(uint2*)(yl + base + 1024) = make_uint2(pack_bf2(l1[0],l1[1]), pack_bf2(l1[2],l1[3]));
}

// ---------------- tensor-core GEMM: ldmatrix + cp.async, bf16 hi/lo split ----------------
// C[M,N] = A @ W^T, A = Ah+Al, W = Wh+Wl, 3 MMA passes (HH, HL, LH).
// Smem: 2 buffers x 4 planes (Ah,Al,Wh,Wl) x [128 rows x 32 bf16 (64B)], SW64 swizzle.
// MODE 0: C fp32. MODE 1: C = acc + X. MODE 2: silu(X)*acc -> (Ch,Cl) planes.
template<int MODE>
__global__ void __launch_bounds__(256) gemm_mma(
    const __nv_bfloat16* __restrict__ Ah, const __nv_bfloat16* __restrict__ Al,
    const __nv_bfloat16* __restrict__ Wh, const __nv_bfloat16* __restrict__ Wl,
    const float* __restrict__ X, float* __restrict__ C,
    __nv_bfloat16* __restrict__ Ch, __nv_bfloat16* __restrict__ Cl,
    int N, int K)
{
    extern __shared__ unsigned char smem[];
    unsigned sbase = (unsigned)__cvta_generic_to_shared(smem);

    int tid = threadIdx.x;
    int bm = blockIdx.y << 7, bn = blockIdx.x << 7;

    // staging: chunk id = row*4 + c (16B chunks); thread -> chunks tid and tid+256
    int r0 = tid >> 2, c0 = tid & 3;
    const __nv_bfloat16* pAh0 = Ah + (size_t)(bm + r0) * K + c0 * 8;
    const __nv_bfloat16* pAh1 = Ah + (size_t)(bm + r0 + 64) * K + c0 * 8;
    const __nv_bfloat16* pAl0 = Al + (size_t)(bm + r0) * K + c0 * 8;
    const __nv_bfloat16* pAl1 = Al + (size_t)(bm + r0 + 64) * K + c0 * 8;
    const __nv_bfloat16* pWh0 = Wh + (size_t)(bn + r0) * K + c0 * 8;
    const __nv_bfloat16* pWh1 = Wh + (size_t)(bn + r0 + 64) * K + c0 * 8;
    const __nv_bfloat16* pWl0 = Wl + (size_t)(bn + r0) * K + c0 * 8;
    const __nv_bfloat16* pWl1 = Wl + (size_t)(bn + r0 + 64) * K + c0 * 8;
    unsigned dOff = SW64(64 * r0 + 16 * c0);   // +4096 for second half (swizzle-invariant)

    // compute mapping
    int warp = tid >> 5, lane = tid & 31;
    int m0 = (warp & 1) << 6;    // 0 / 64
    int n0 = (warp >> 1) << 5;   // 0,32,64,96
    int lr = lane & 15;          // ldmatrix row within 16
    int lc = lane >> 4;          // ldmatrix k-half (0/1)
    unsigned aOff[4], bOff[2];
    #pragma unroll
    for (int i = 0; i < 4; i++) aOff[i] = 64u * (m0 + 16 * i + lr) + 16u * lc;
    #pragma unroll
    for (int j = 0; j < 2; j++) bOff[j] = 64u * (n0 + 16 * j + lr) + 16u * lc;

    int fr = lane >> 2, kp = lane & 3;

    float acc[4][4][4];
    #pragma unroll
    for (int i = 0; i < 4; i++)
        #pragma unroll
        for (int j = 0; j < 4; j++)
            #pragma unroll
            for (int r = 0; r < 4; r++) acc[i][j][r] = 0.0f;

    int nk = K >> 5;

    // prologue: stage k-chunk 0 into buffer 0
    {
        unsigned b0 = sbase;
        CPA16(b0 + dOff,          pAh0);
        CPA16(b0 + dOff + 4096,   pAh1);
        CPA16(b0 + 8192  + dOff,        pAl0);
        CPA16(b0 + 8192  + dOff + 4096, pAl1);
        CPA16(b0 + 16384 + dOff,        pWh0);
        CPA16(b0 + 16384 + dOff + 4096, pWh1);
        CPA16(b0 + 24576 + dOff,        pWl0);
        CPA16(b0 + 24576 + dOff + 4096, pWl1);
        CPCOMMIT();
    }

    for (int kb = 0; kb < nk; kb++) {
        CPWAIT0();
        __syncthreads();
        if (kb + 1 < nk) {
            int ko = (kb + 1) << 5;
            unsigned b0 = sbase + (((kb + 1) & 1) << 15);
            CPA16(b0 + dOff,          pAh0 + ko);
            CPA16(b0 + dOff + 4096,   pAh1 + ko);
            CPA16(b0 + 8192  + dOff,        pAl0 + ko);
            CPA16(b0 + 8192  + dOff + 4096, pAl1 + ko);
            CPA16(b0 + 16384 + dOff,        pWh0 + ko);
            CPA16(b0 + 16384 + dOff + 4096, pWh1 + ko);
            CPA16(b0 + 24576 + dOff,        pWl0 + ko);
            CPA16(b0 + 24576 + dOff + 4096, pWl1 + ko);
            CPCOMMIT();
        }

        unsigned bAh = sbase + ((kb & 1) << 15);
        unsigned bAl = bAh + 8192, bWh = bAh + 16384, bWl = bAh + 24576;

        #pragma unroll
        for (int s = 0; s < 2; s++) {
            unsigned so = s << 5;
            unsigned aH[4][4], aL[4][4], bH[2][4], bL[2][4];
            #pragma unroll
            for (int i = 0; i < 4; i++) LDSM4(aH[i], bAh + SW64(aOff[i] + so));
            #pragma unroll
            for (int j = 0; j < 2; j++) LDSM4(bH[j], bWh + SW64(bOff[j] + so));
            #pragma unroll
            for (int i = 0; i < 4; i++)
                #pragma unroll
                for (int j = 0; j < 2; j++) {
                    MMA_B16(acc[i][2*j],   aH[i], bH[j][0], bH[j][2]);
                    MMA_B16(acc[i][2*j+1], aH[i], bH[j][1], bH[j][3]);
                }
            #pragma unroll
            for (int j = 0; j < 2; j++) LDSM4(bL[j], bWl + SW64(bOff[j] + so));
            #pragma unroll
            for (int i = 0; i < 4; i++)
                #pragma unroll
                for (int j = 0; j < 2; j++) {
                    MMA_B16(acc[i][2*j],   aH[i], bL[j][0], bL[j][2]);
                    MMA_B16(acc[i][2*j+1], aH[i], bL[j][1], bL[j][3]);
                }
            #pragma unroll
            for (int i = 0; i < 4; i++) LDSM4(aL[i], bAl + SW64(aOff[i] + so));
            #pragma unroll
            for (int i = 0; i < 4; i++)
                #pragma unroll
                for (int j = 0; j < 2; j++) {
                    MMA_B16(acc[i][2*j],   aL[i], bH[j][0], bH[j][2]);
                    MMA_B16(acc[i][2*j+1], aL[i], bH[j][1], bH[j][3]);
                }
        }
        __syncthreads();
    }

    // epilogue
    #pragma unroll
    for (int i = 0; i < 4; i++) {
        #pragma unroll
        for (int j = 0; j < 4; j++) {
            int row0 = bm + m0 + 16 * i + fr;
            int col  = bn + n0 + 8 * j + kp * 2;
            #pragma unroll
            for (int half = 0; half < 2; half++) {
                int row = row0 + half * 8;
                float v0 = acc[i][j][2 * half + 0];
                float v1 = acc[i][j][2 * half + 1];
                size_t off = (size_t)row * N + col;
                if (MODE == 0) {
                    *(float2*)(C + off) = make_float2(v0, v1);
                } else if (MODE == 1) {
                    float2 xr = *(const float2*)(X + off);
                    *(float2*)(C + off) = make_float2(v0 + xr.x, v1 + xr.y);
                } else {
                    float2 gr = *(const float2*)(X + off);
                    v0 *= gr.x / (1.0f + expf(-gr.x));
                    v1 *= gr.y / (1.0f + expf(-gr.y));
                    float h0, l0, h1, l1;
                    split1(v0, h0, l0);
                    split1(v1, h1, l1);
                    *(unsigned*)(Ch + off) = pack_bf2(h0, h1);
                    *(unsigned*)(Cl + off) = pack_bf2(l0, l1);
                }
            }
        }
    }
}

// ---------------- RoPE (in-place on g_q and g_k) ----------------
__global__ void rope_kernel(const int* __restrict__ pos_ids) {
    int gid = blockIdx.x * blockDim.x + threadIdx.x;
    int d = gid & 31;
    int slot = gid >> 5;
    int head = slot % (NH + NKV);
    int tok = slot / (NH + NKV);
    if (tok >= M_TOK) return;
    float p = (float)pos_ids[tok];
    float inv = powf(10000.0f, -(float)d * (1.0f / 32.0f));
    float ang = p * inv;
    float s, c;
    sincosf(ang, &s, &c);
    float* base;
    if (head < NH) base = g_q + (((size_t)tok * NH + head) << 6);
    else           base = g_k + (((size_t)tok * NKV + (head - NH)) << 6);
    float x1 = base[d];
    float x2 = base[d + 32];
    base[d]      = x1 * c - x2 * s;
    base[d + 32] = x2 * c + x1 * s;
}

// ---------------- Flash attention (causal, GQA) -> bf16 hi/lo planes ----------------
__global__ void __launch_bounds__(256, 1) attn_kernel() {
    extern __shared__ float sm[];
    float* Qt  = sm;
    float* KtT = sm + 64 * 68;
    float* Vt  = sm + 2 * 64 * 68;
    float* St  = sm + 3 * 64 * 68;

    int qt = blockIdx.x, h = blockIdx.y, b = blockIdx.z;
    int kh = h >> 2;
    int tid = threadIdx.x;

    for (int i = tid; i < 1024; i += 256) {
        int r = i >> 4, c4 = (i & 15) << 2;
        const float* src = g_q + (((size_t)(b * SEQ + (qt << 6) + r) * NH + h) << 6) + c4;
        float4 qv = *(const float4*)src;
        float* dst = &Qt[r * 68 + c4];
        dst[0] = qv.x * 0.125f; dst[1] = qv.y * 0.125f;
        dst[2] = qv.z * 0.125f; dst[3] = qv.w * 0.125f;
    }

    int qr = tid >> 2, qc = tid & 3;
    int pi = tid >> 4, pj = tid & 15;
    int qr0 = pi << 2, kc0 = pj << 2;

    float acc[16];
    #pragma unroll
    for (int d = 0; d < 16; d++) acc[d] = 0.0f;
    float mrow = -INFINITY, lrow = 0.0f;

    for (int kt = 0; kt <= qt; kt++) {
        __syncthreads();
        int tokbase = b * SEQ + (kt << 6);
        for (int i = tid; i < 1024; i += 256) {
            int r = i & 63, c4 = (i >> 6) << 2;
            const float* src = g_k + (((size_t)(tokbase + r) * NKV + kh) << 6) + c4;
            float4 kv = *(const float4*)src;
            KtT[(c4 + 0) * 68 + r] = kv.x;
            KtT[(c4 + 1) * 68 + r] = kv.y;
            KtT[(c4 + 2) * 68 + r] = kv.z;
            KtT[(c4 + 3) * 68 + r] = kv.w;
        }
        for (int i = tid; i < 1024; i += 256) {
            int r = i >> 4, c4 = (i & 15) << 2;
            const float* src = g_v + (((size_t)(tokbase + r) * NKV + kh) << 6) + c4;
            *(float4*)&Vt[r * 68 + c4] = *(const float4*)src;
        }
        __syncthreads();

        float sacc[4][4];
        #pragma unroll
        for (int i = 0; i < 4; i++)
            #pragma unroll
            for (int j = 0; j < 4; j++) sacc[i][j] = 0.0f;
        #pragma unroll
        for (int d4 = 0; d4 < 64; d4 += 4) {
            float aq[4][4], bk[4][4];
            #pragma unroll
            for (int i = 0; i < 4; i++)
                *(float4*)aq[i] = *(const float4*)&Qt[(qr0 + i) * 68 + d4];
            #pragma unroll
            for (int dd = 0; dd < 4; dd++)
                *(float4*)bk[dd] = *(const float4*)&KtT[(d4 + dd) * 68 + kc0];
            #pragma unroll
            for (int i = 0; i < 4; i++)
                #pragma unroll
                for (int dd = 0; dd < 4; dd++)
                    #pragma unroll
                    for (int j = 0; j < 4; j++)
                        sacc[i][j] += aq[i][dd] * bk[dd][j];
        }
        bool diag = (kt == qt);
        #pragma unroll
        for (int i = 0; i < 4; i++) {
            int qg = (qt << 6) + qr0 + i;
            float4 r;
            float v0 = sacc[i][0], v1 = sacc[i][1], v2 = sacc[i][2], v3 = sacc[i][3];
            if (diag) {
                int kg = (kt << 6) + kc0;
                if (kg + 0 > qg) v0 = -INFINITY;
                if (kg + 1 > qg) v1 = -INFINITY;
                if (kg + 2 > qg) v2 = -INFINITY;
                if (kg + 3 > qg) v3 = -INFINITY;
            }
            r.x = v0; r.y = v1; r.z = v2; r.w = v3;
            *(float4*)&St[(qr0 + i) * 68 + kc0] = r;
        }
        __syncthreads();

        float* srow = &St[qr * 68 + (qc << 4)];
        float tmax = -INFINITY;
        #pragma unroll
        for (int j = 0; j < 16; j++) tmax = fmaxf(tmax, srow[j]);
        tmax = fmaxf(tmax, __shfl_xor_sync(0xffffffffu, tmax, 1));
        tmax = fmaxf(tmax, __shfl_xor_sync(0xffffffffu, tmax, 2));
        float mnew = fmaxf(mrow, tmax);
        float corr = __expf(mrow - mnew);
        float psum = 0.0f;
        #pragma unroll
        for (int j = 0; j < 16; j++) {
            float pv = __expf(srow[j] - mnew);
            srow[j] = pv;
            psum += pv;
        }
        psum += __shfl_xor_sync(0xffffffffu, psum, 1);
        psum += __shfl_xor_sync(0xffffffffu, psum, 2);
        lrow = lrow * corr + psum;
        mrow = mnew;
        #pragma unroll
        for (int d = 0; d < 16; d++) acc[d] *= corr;
        __syncwarp();

        for (int kc = 0; kc < 64; kc++) {
            float pv = St[qr * 68 + kc];
            const float4 v0 = *(const float4*)&Vt[kc * 68 + (qc << 4) + 0];
            const float4 v1 = *(const float4*)&Vt[kc * 68 + (qc << 4) + 4];
            const float4 v2 = *(const float4*)&Vt[kc * 68 + (qc << 4) + 8];
            const float4 v3 = *(const float4*)&Vt[kc * 68 + (qc << 4) + 12];
            acc[0]  += pv * v0.x; acc[1]  += pv * v0.y; acc[2]  += pv * v0.z; acc[3]  += pv * v0.w;
            acc[4]  += pv * v1.x; acc[5]  += pv * v1.y; acc[6]  += pv * v1.z; acc[7]  += pv * v1.w;
            acc[8]  += pv * v2.x; acc[9]  += pv * v2.y; acc[10] += pv * v2.z; acc[11] += pv * v2.w;
            acc[12] += pv * v3.x; acc[13] += pv * v3.y; acc[14] += pv * v3.z; acc[15] += pv * v3.w;
        }
    }

    float inv_l = 1.0f / lrow;
    float o[16], oh[16], ol[16];
    #pragma unroll
    for (int d = 0; d < 16; d++) {
        o[d] = acc[d] * inv_l;
        split1(o[d], oh[d], ol[d]);
    }
    size_t idx = (((size_t)(b * SEQ + (qt << 6) + qr) * NH + h) << 6) + (qc << 4);
    uint4 ph0 = make_uint4(pack_bf2(oh[0],oh[1]), pack_bf2(oh[2],oh[3]),
                           pack_bf2(oh[4],oh[5]), pack_bf2(oh[6],oh[7]));
    uint4 ph1 = make_uint4(pack_bf2(oh[8],oh[9]), pack_bf2(oh[10],oh[11]),
                           pack_bf2(oh[12],oh[13]), pack_bf2(oh[14],oh[15]));
    uint4 pl0 = make_uint4(pack_bf2(ol[0],ol[1]), pack_bf2(ol[2],ol[3]),
                           pack_bf2(ol[4],ol[5]), pack_bf2(ol[6],ol[7]));
    uint4 pl1 = make_uint4(pack_bf2(ol[8],ol[9]), pack_bf2(ol[10],ol[11]),
                           pack_bf2(ol[12],ol[13]), pack_bf2(ol[14],ol[15]));
    *(uint4*)(g_ao_h + idx)     = ph0;
    *(uint4*)(g_ao_h + idx + 8) = ph1;
    *(uint4*)(g_ao_l + idx)     = pl0;
    *(uint4*)(g_ao_l + idx + 8) = pl1;
}

// ---------------- launch ----------------
extern "C" void kernel_launch(void* const* d_in, const int* in_sizes, int n_in,
                              void* d_out, int out_size) {
    (void)in_sizes; (void)n_in; (void)out_size;
    const float* hs     = (const float*)d_in[0];
    const int*   pos    = (const int*)d_in[2];
    const float* q_w    = (const float*)d_in[3];
    const float* k_w    = (const float*)d_in[4];
    const float* v_w    = (const float*)d_in[5];
    const float* o_w    = (const float*)d_in[6];
    const float* gate_w = (const float*)d_in[7];
    const float* up_w   = (const float*)d_in[8];
    const float* down_w = (const float*)d_in[9];
    const float* ln1    = (const float*)d_in[10];
    const float* ln2    = (const float*)d_in[11];
    const float* kkp    = (const float*)d_in[12];
    const float* aap    = (const float*)d_in[13];
    float* out = (float*)d_out;

    float *q, *k, *v, *hid, *gate;
    __nv_bfloat16 *xnh, *xnl, *aoh, *aol, *acth, *actl, *wh, *wl;
    cudaGetSymbolAddress((void**)&q,    g_q);
    cudaGetSymbolAddress((void**)&k,    g_k);
    cudaGetSymbolAddress((void**)&v,    g_v);
    cudaGetSymbolAddress((void**)&hid,  g_hidden);
    cudaGetSymbolAddress((void**)&gate, g_gate);
    cudaGetSymbolAddress((void**)&xnh,  g_xn_h);
    cudaGetSymbolAddress((void**)&xnl,  g_xn_l);
    cudaGetSymbolAddress((void**)&aoh,  g_ao_h);
    cudaGetSymbolAddress((void**)&aol,  g_ao_l);
    cudaGetSymbolAddress((void**)&acth, g_act_h);
    cudaGetSymbolAddress((void**)&actl, g_act_l);
    cudaGetSymbolAddress((void**)&wh,   g_w_h);
    cudaGetSymbolAddress((void**)&wl,   g_w_l);

    cudaFuncSetAttribute(attn_kernel, cudaFuncAttributeMaxDynamicSharedMemorySize, ATTN_SMEM);
    cudaFuncSetAttribute(gemm_mma<0>, cudaFuncAttributeMaxDynamicSharedMemorySize, GEMM_SMEM);
    cudaFuncSetAttribute(gemm_mma<1>, cudaFuncAttributeMaxDynamicSharedMemorySize, GEMM_SMEM);
    cudaFuncSetAttribute(gemm_mma<2>, cudaFuncAttributeMaxDynamicSharedMemorySize, GEMM_SMEM);

    dim3 blk(256);

    // 0) weight prepass: binarize + bf16 split
    binsplit_kernel<<<(2048*2048)/1024, blk>>>(q_w,    wh + OFF_Q, wl + OFF_Q, kkp, aap);
    binsplit_kernel<<<(512*2048)/1024,  blk>>>(k_w,    wh + OFF_K, wl + OFF_K, kkp, aap);
    binsplit_kernel<<<(512*2048)/1024,  blk>>>(v_w,    wh + OFF_V, wl + OFF_V, kkp, aap);
    binsplit_kernel<<<(2048*2048)/1024, blk>>>(o_w,    wh + OFF_O, wl + OFF_O, kkp, aap);
    binsplit_kernel<<<(5632*2048)/1024, blk>>>(gate_w, wh + OFF_G, wl + OFF_G, kkp, aap);
    binsplit_kernel<<<(5632*2048)/1024, blk>>>(up_w,   wh + OFF_U, wl + OFF_U, kkp, aap);
    binsplit_kernel<<<(2048*5632)/1024, blk>>>(down_w, wh + OFF_D, wl + OFF_D, kkp, aap);

    // 1) rmsnorm 1 -> planes
    rmsnorm_kernel<<<M_TOK, blk>>>(hs, ln1, xnh, xnl);
    // 2) q/k/v projections
    gemm_mma<0><<<dim3(H/128, M_TOK/128), blk, GEMM_SMEM>>>(xnh, xnl, wh+OFF_Q, wl+OFF_Q, nullptr, q, nullptr, nullptr, H, H);
    gemm_mma<0><<<dim3((NKV*HD)/128, M_TOK/128), blk, GEMM_SMEM>>>(xnh, xnl, wh+OFF_K, wl+OFF_K, nullptr, k, nullptr, nullptr, NKV*HD, H);
    gemm_mma<0><<<dim3((NKV*HD)/128, M_TOK/128), blk, GEMM_SMEM>>>(xnh, xnl, wh+OFF_V, wl+OFF_V, nullptr, v, nullptr, nullptr, NKV*HD, H);
    // 3) rope
    rope_kernel<<<(M_TOK*(NH+NKV)*32)/256, blk>>>(pos);
    // 4) attention -> ao planes
    attn_kernel<<<dim3(SEQ/64, NH, BATCH), blk, ATTN_SMEM>>>();
    // 5) o-proj + residual
    gemm_mma<1><<<dim3(H/128, M_TOK/128), blk, GEMM_SMEM>>>(aoh, aol, wh+OFF_O, wl+OFF_O, hs, hid, nullptr, nullptr, H, H);
    // 6) rmsnorm 2 -> planes
    rmsnorm_kernel<<<M_TOK, blk>>>(hid, ln2, xnh, xnl);
    // 7) gate proj (fp32 out)
    gemm_mma<0><<<dim3(FF/128, M_TOK/128), blk, GEMM_SMEM>>>(xnh, xnl, wh+OFF_G, wl+OFF_G, nullptr, gate, nullptr, nullptr, FF, H);
    // 8) up proj, fused silu(gate)*up -> act planes
    gemm_mma<2><<<dim3(FF/128, M_TOK/128), blk, GEMM_SMEM>>>(xnh, xnl, wh+OFF_U, wl+OFF_U, gate, nullptr, acth, actl, FF, H);
    // 9) down proj + residual -> out
    gemm_mma<1><<<dim3(H/128, M_TOK/128), blk, GEMM_SMEM>>>(acth, actl, wh+OFF_D, wl+OFF_D, hid, out, nullptr, nullptr, H, FF);
}